// round 8
// baseline (speedup 1.0000x reference)
#include <cuda_runtime.h>
#include <cuda_bf16.h>
#include <cstdint>

// NnInteractionTokenizer: bond = x[row]*x[col]; local_field = segsum(bond, row);
// tokens = relu(relu([x, lf] @ w1^T + b1) @ w2^T + b2)
//
// local_field[r] = x[r] * sum_{e: row[e]=r} x[col[e]] -> edge phase only
// accumulates x[col[e]] into g_acc[row[e]]; x[r] multiply folds into node phase.
//
// R8: random x-gathers moved OUT of the L1tex pipe (32-wavefront/warp cost)
// into SMEM: a 2-CTA cluster holds all of x (50K floats per CTA), gathers go
// through mapa + ld.shared::cluster (random smem ~N=4 bank cyc/warp).
// Persistent grid: 148 CTAs (74 clusters), x loaded once, chunk-strided edges.
//
// g_acc invariant: __device__ globals start zeroed; node_kernel re-zeroes
// g_acc[n] from the same thread that read it -> zero at every replay entry.

#define N_NODES 100000
#define HALF_NODES 50000
#define N_EDGES 6400000
#define TD 16
#define EPT 4
#define EBLK 1024                       // threads per edge CTA
#define CHUNK (EBLK * EPT)              // 4096 edges per chunk
#define NCHUNKS ((N_EDGES + CHUNK - 1) / CHUNK)   // 1563
#define EGRID 148                       // persistent CTAs (74 clusters of 2)
#define SMEM_X_BYTES (HALF_NODES * 4)   // 195.3 KB dynamic smem

__device__ float g_acc[N_NODES];

__device__ __forceinline__ uint32_t smem_u32(const void* p) {
    uint32_t a;
    asm("{ .reg .u64 t; cvta.to.shared.u64 t, %1; cvt.u32.u64 %0, t; }"
        : "=r"(a) : "l"(p));
    return a;
}

__device__ __forceinline__ uint32_t ctarank() {
    uint32_t r;
    asm("mov.u32 %0, %%cluster_ctarank;" : "=r"(r));
    return r;
}

// Gather x[col] from cluster-distributed smem. rank = owning CTA, offset local.
__device__ __forceinline__ float cluster_gather(uint32_t sbase, int col) {
    uint32_t rk  = (col >= HALF_NODES) ? 1u : 0u;
    uint32_t off = sbase + ((uint32_t)col - rk * (uint32_t)HALF_NODES) * 4u;
    uint32_t ra, v;
    asm("mapa.shared::cluster.u32 %0, %1, %2;" : "=r"(ra) : "r"(off), "r"(rk));
    asm volatile("ld.shared::cluster.b32 %0, [%1];" : "=r"(v) : "r"(ra));
    return __uint_as_float(v);
}

// ---------------------------------------------------------------------------
// Edge phase. Dtype probe per CTA (uniform): int64 edge data (< 2^17, LE) has
// all odd uint32 words zero; int32 data has random words -> P(8 zeros) ~ 1e-40.
// ---------------------------------------------------------------------------
__global__ void __launch_bounds__(EBLK, 1) __cluster_dims__(2, 1, 1)
edge_kernel(const void* __restrict__ ei, const float* __restrict__ x) {
    extern __shared__ float sx[];       // my half of x: 50000 floats
    __shared__ int s_is64;

    const uint32_t rank = ctarank();
    const int t = threadIdx.x;

    // Stage this CTA's half of x (coalesced).
    const float* xh = x + rank * HALF_NODES;
    for (int i = t; i < HALF_NODES; i += EBLK) sx[i] = xh[i];

    if (t == 0) {
        const unsigned int* w = (const unsigned int*)ei;
        unsigned int acc = 0;
#pragma unroll
        for (int k = 0; k < 8; k++) acc |= w[2 * k + 1];
        s_is64 = (acc == 0u) ? 1 : 0;
    }
    __syncthreads();                    // publish s_is64 + local sx
    asm volatile("barrier.cluster.arrive.aligned;" ::: "memory");
    asm volatile("barrier.cluster.wait.aligned;" ::: "memory");  // peer sx ready

    const uint32_t sbase = smem_u32(sx);
    const int is64 = s_is64;
    const int cta = blockIdx.x;

    for (int chunk = cta; chunk < NCHUNKS; chunk += EGRID) {
        const long long base = (long long)chunk * CHUNK + (long long)t * EPT;
        if (base >= N_EDGES) continue;

        int r[EPT], c[EPT];
        if (is64) {
            const longlong2* row = (const longlong2*)ei;       // edge_index[0]
            const longlong2* col = row + (N_EDGES / 2);        // edge_index[1]
            longlong2 r0 = __ldg(&row[base / 2]);
            longlong2 r1 = __ldg(&row[base / 2 + 1]);
            longlong2 c0 = __ldg(&col[base / 2]);
            longlong2 c1 = __ldg(&col[base / 2 + 1]);
            r[0] = (int)r0.x; r[1] = (int)r0.y; r[2] = (int)r1.x; r[3] = (int)r1.y;
            c[0] = (int)c0.x; c[1] = (int)c0.y; c[2] = (int)c1.x; c[3] = (int)c1.y;
        } else {
            const int4* row = (const int4*)ei;
            const int4* col = row + (N_EDGES / 4);
            int4 rv = __ldg(&row[base / 4]);
            int4 cv = __ldg(&col[base / 4]);
            r[0] = rv.x; r[1] = rv.y; r[2] = rv.z; r[3] = rv.w;
            c[0] = cv.x; c[1] = cv.y; c[2] = cv.z; c[3] = cv.w;
        }

        float v[EPT];
#pragma unroll
        for (int k = 0; k < EPT; k++) v[k] = cluster_gather(sbase, c[k]);
#pragma unroll
        for (int k = 0; k < EPT; k++) atomicAdd(&g_acc[r[k]], v[k]);
    }

    // No CTA may exit while its peer might still read its smem.
    asm volatile("barrier.cluster.arrive.aligned;" ::: "memory");
    asm volatile("barrier.cluster.wait.aligned;" ::: "memory");
}

// ---------------------------------------------------------------------------
// Node phase (R7 form, measured 7.4us): 1 thread/node, loads issued before the
// weight barrier, same-thread g_acc read->clear, LDS.128 layer-2 weights.
// ---------------------------------------------------------------------------
__global__ void __launch_bounds__(256) node_kernel(const float* __restrict__ x,
                                                   const float* __restrict__ w1,
                                                   const float* __restrict__ b1,
                                                   const float* __restrict__ w2,
                                                   const float* __restrict__ b2,
                                                   float* __restrict__ out) {
    __shared__ float sw1[2 * TD];
    __shared__ float sb1[TD];
    __shared__ __align__(16) float sw2[TD * TD];
    __shared__ float sb2[TD];

    const int t = threadIdx.x;
    const int n = blockIdx.x * 256 + t;
    const bool act = (n < N_NODES);

    float s = 0.f, lfa = 0.f;
    if (act) { s = x[n]; lfa = g_acc[n]; }

    if (t < 2 * TD) sw1[t] = w1[t];
    if (t < TD) { sb1[t] = b1[t]; sb2[t] = b2[t]; }
    sw2[t] = w2[t];
    __syncthreads();

    if (act) g_acc[n] = 0.0f;   // same thread, same address: ordered after read

    const float lf = s * lfa;

    float h[TD];
#pragma unroll
    for (int j = 0; j < TD; j++) {
        float v = fmaf(sw1[2 * j + 1], lf, fmaf(sw1[2 * j], s, sb1[j]));
        h[j] = v > 0.f ? v : 0.f;
    }

    float4* o = (float4*)(out + (size_t)n * TD);
#pragma unroll
    for (int k4 = 0; k4 < 4; k4++) {
        float4 res;
        float* rp = (float*)&res;
#pragma unroll
        for (int kk = 0; kk < 4; kk++) {
            const int k = k4 * 4 + kk;
            float v = sb2[k];
            const float4* wrow = (const float4*)&sw2[k * TD];
#pragma unroll
            for (int j4 = 0; j4 < 4; j4++) {
                float4 w = wrow[j4];
                v = fmaf(w.x, h[j4 * 4 + 0], v);
                v = fmaf(w.y, h[j4 * 4 + 1], v);
                v = fmaf(w.z, h[j4 * 4 + 2], v);
                v = fmaf(w.w, h[j4 * 4 + 3], v);
            }
            rp[kk] = v > 0.f ? v : 0.f;
        }
        if (act) o[k4] = res;
    }
}

extern "C" void kernel_launch(void* const* d_in, const int* in_sizes, int n_in,
                              void* d_out, int out_size) {
    const float* x  = (const float*)d_in[0];
    const void*  ei = d_in[1];
    const float* w1 = (const float*)d_in[2];
    const float* b1 = (const float*)d_in[3];
    const float* w2 = (const float*)d_in[4];
    const float* b2 = (const float*)d_in[5];
    float* out = (float*)d_out;

    static int smem_set = 0;
    if (!smem_set) {
        cudaFuncSetAttribute(edge_kernel,
                             cudaFuncAttributeMaxDynamicSharedMemorySize,
                             SMEM_X_BYTES);
        smem_set = 1;
    }

    edge_kernel<<<EGRID, EBLK, SMEM_X_BYTES>>>(ei, x);
    node_kernel<<<(N_NODES + 255) / 256, 256>>>(x, w1, b1, w2, b2, out);
}